// round 3
// baseline (speedup 1.0000x reference)
#include <cuda_runtime.h>

// RoiPoolingConv v3: register-sliding row kernel.
//   Precompute: per-(roi,px) x-table and per-(roi,py) y-table (corner index,
//               corner index, frac) — one tiny kernel, 3584 threads.
//   Main: CTA = (roi, py), 128 threads (one float4 channel lane each).
//         Thread walks px 0..13 keeping current corner columns (2 cols x
//         2 rows of float4) in registers; x0/x1 are monotone so most steps
//         shift/reuse instead of reloading. Avg loads/px drops 4 -> ~3.2.

struct __align__(16) Entry { int i0; int i1; float f; float pad; };

#define MAXENT 8192   // >= num_rois * pool (256*14 = 3584)
__device__ Entry g_xt[MAXENT];   // per (roi,px): global x0, x1, fx
__device__ Entry g_yt[MAXENT];   // per (roi,py): (y0)*W, (y1)*W, fy

__global__ void roi_tables_kernel(const int* __restrict__ rois,
                                  int n, int pool, int W)
{
    int t = blockIdx.x * blockDim.x + threadIdx.x;
    if (t >= n) return;
    int r = t / pool;
    int i = t - r * pool;

    const int4 roi = __ldg(((const int4*)rois) + r);
    const float poolf = (float)pool;
    const float ip5   = (float)i + 0.5f;

    // x axis — fp32 sequence must match reference up to the floor
    {
        float wf    = (float)roi.z;
        float scale = __fdiv_rn(wf, poolf);
        float s     = __fsub_rn(__fmul_rn(ip5, scale), 0.5f);
        s = fminf(fmaxf(s, 0.0f), wf - 1.0f);
        int i0 = (int)s;
        int i1 = min(i0 + 1, roi.z - 1);
        Entry e;
        e.i0 = roi.x + i0;
        e.i1 = roi.x + i1;
        e.f  = s - (float)i0;
        e.pad = 0.0f;
        g_xt[t] = e;
    }
    // y axis
    {
        float hf    = (float)roi.w;
        float scale = __fdiv_rn(hf, poolf);
        float s     = __fsub_rn(__fmul_rn(ip5, scale), 0.5f);
        s = fminf(fmaxf(s, 0.0f), hf - 1.0f);
        int i0 = (int)s;
        int i1 = min(i0 + 1, roi.w - 1);
        Entry e;
        e.i0 = (roi.y + i0) * W;
        e.i1 = (roi.y + i1) * W;
        e.f  = s - (float)i0;
        e.pad = 0.0f;
        g_yt[t] = e;
    }
}

__global__ void __launch_bounds__(128)
roi_slide_kernel(const float* __restrict__ img,
                 float*       __restrict__ out,
                 int pool, int C4)
{
    const int blk = blockIdx.x;
    const int py  = blk % pool;
    const int r   = blk / pool;
    const int c4  = threadIdx.x;

    const Entry ye = g_yt[blk];           // warp-uniform 16B load
    const float fy = ye.f, gy = 1.0f - fy;

    const float4* img4 = (const float4*)img;
    const float4* rowT = img4 + (size_t)ye.i0 * C4 + c4;
    const float4* rowB = img4 + (size_t)ye.i1 * C4 + c4;
    float4* o = (float4*)out + (size_t)blk * pool * C4 + c4;

    const Entry* xt = &g_xt[r * pool];

    int cx0 = -1, cx1 = -1;
    float4 t0 = {0,0,0,0}, t1 = {0,0,0,0}, b0 = {0,0,0,0}, b1 = {0,0,0,0};

    for (int px = 0; px < pool; ++px) {
        const Entry xe = xt[px];          // warp-uniform, L1-hot
        const int nx0 = xe.i0, nx1 = xe.i1;
        const float fx = xe.f, gx = 1.0f - fx;

        if (nx0 != cx0) {
            if (nx0 == cx1) { t0 = t1; b0 = b1; }
            else {
                t0 = __ldg(rowT + nx0 * C4);
                b0 = __ldg(rowB + nx0 * C4);
            }
            cx0 = nx0;
        }
        if (nx1 != cx1) {
            if (nx1 == cx0) { t1 = t0; b1 = b0; }
            else {
                t1 = __ldg(rowT + nx1 * C4);
                b1 = __ldg(rowB + nx1 * C4);
            }
            cx1 = nx1;
        }

        const float w00 = gx * gy, w01 = fx * gy;
        const float w10 = gx * fy, w11 = fx * fy;

        float4 res;
        res.x = t0.x * w00 + t1.x * w01 + b0.x * w10 + b1.x * w11;
        res.y = t0.y * w00 + t1.y * w01 + b0.y * w10 + b1.y * w11;
        res.z = t0.z * w00 + t1.z * w01 + b0.z * w10 + b1.z * w11;
        res.w = t0.w * w00 + t1.w * w01 + b0.w * w10 + b1.w * w11;

        o[px * C4] = res;
    }
}

extern "C" void kernel_launch(void* const* d_in, const int* in_sizes, int n_in,
                              void* d_out, int out_size)
{
    const float* img  = (const float*)d_in[0];
    const int*   rois = (const int*)d_in[1];
    float*       out  = (float*)d_out;

    const int H = 128, W = 128;
    const int C        = in_sizes[0] / (H * W);      // 512
    const int num_rois = in_sizes[1] / 4;            // 256

    const int pp = out_size / (num_rois * C);
    int pool = 1;
    while (pool * pool < pp) pool++;                 // 14

    const int n_tab = num_rois * pool;               // 3584
    roi_tables_kernel<<<(n_tab + 127) / 128, 128>>>(rois, n_tab, pool, W);

    roi_slide_kernel<<<n_tab, 128>>>(img, out, pool, C >> 2);
}